// round 6
// baseline (speedup 1.0000x reference)
#include <cuda_runtime.h>
#include <cuda_bf16.h>
#include <cstdint>

// Problem shape (fixed by reference): n=32, m=16, p=1024, d=512
//   task: [32, 16, 1024] f32
//   feat: [32, 1024, 512] f32
//   out : [32, 1024, 512] f32 = feat * mean_m(task)
#define N_DIM 32
#define M_DIM 16
#define P_DIM 1024
#define D_DIM 512

#define ROWS_PER_BLOCK 64                       // 1024 % 64 == 0 -> never straddles an n boundary
#define F4_PER_ROW (D_DIM / 4)                  // 128
#define F4_PER_BLOCK (ROWS_PER_BLOCK * F4_PER_ROW)  // 8192
#define BATCHES 8
#define F4_PER_BATCH (F4_PER_BLOCK / BATCHES)   // 1024 f4/batch = 4 f4/thread
#define NUM_BLOCKS ((N_DIM * P_DIM) / ROWS_PER_BLOCK) // 512 -> ~3.5 CTAs/SM, single wave

__global__ void __launch_bounds__(256, 4) fused_kernel(const float* __restrict__ task,
                                                       const float4* __restrict__ feat,
                                                       float4* __restrict__ out) {
    __shared__ float s_part[256];
    __shared__ float s_scale[ROWS_PER_BLOCK];

    const int t = threadIdx.x;
    const int block_row0 = blockIdx.x * ROWS_PER_BLOCK;   // global row = n*1024 + p

    // ---- Phase 1: means for 64 rows. 64 rows x 16 m = 1024 task elems, 4/thread.
    // thread t: p_local = t&63, m in {t>>6, +4, +8, +12} -> coalesced per m-slice.
    {
        const int p_local = t & 63;
        const int m0      = t >> 6;            // 0..3
        const int grow = block_row0 + p_local;
        const int n = grow >> 10;
        const int p = grow & (P_DIM - 1);
        const float* tb = task + (size_t)n * (M_DIM * P_DIM) + p;
        float s = 0.0f;
        #pragma unroll
        for (int j = 0; j < 4; ++j)
            s += tb[(size_t)(m0 + 4 * j) * P_DIM];
        s_part[t] = s;
    }
    __syncthreads();
    if (t < ROWS_PER_BLOCK) {
        float s = s_part[t] + s_part[t + 64] + s_part[t + 128] + s_part[t + 192];
        s_scale[t] = s * (1.0f / M_DIM);
    }
    __syncthreads();

    // ---- Phase 2: 8192 f4 per block, 8 batches of 4 f4/thread, ping-pong
    // register double-buffer so >=4 independent LDG.128 stay in flight. ----
    const size_t base = (size_t)block_row0 * F4_PER_ROW;

    float4 buf[2][4];
    #pragma unroll
    for (int i = 0; i < 4; ++i)
        buf[0][i] = feat[base + (size_t)(i * 256 + t)];

    #pragma unroll
    for (int k = 0; k < BATCHES; ++k) {
        const int cur = k & 1;
        if (k < BATCHES - 1) {
            const int off = (k + 1) * F4_PER_BATCH;
            #pragma unroll
            for (int i = 0; i < 4; ++i)
                buf[cur ^ 1][i] = feat[base + (size_t)(off + i * 256 + t)];
        }
        const int off = k * F4_PER_BATCH;
        #pragma unroll
        for (int i = 0; i < 4; ++i) {
            const int idx_local = off + i * 256 + t;
            const float s = s_scale[idx_local >> 7];
            float4 x = buf[cur][i];
            x.x *= s; x.y *= s; x.z *= s; x.w *= s;
            __stcs(&out[base + idx_local], x);   // evict-first: protect feat's L2 residency
        }
    }
}

extern "C" void kernel_launch(void* const* d_in, const int* in_sizes, int n_in,
                              void* d_out, int out_size) {
    const float* task = (const float*)d_in[0];
    const float* feat = (const float*)d_in[1];
    float* out = (float*)d_out;

    fused_kernel<<<NUM_BLOCKS, 256>>>(task, (const float4*)feat, (float4*)out);
}

// round 7
// speedup vs baseline: 1.0015x; 1.0015x over previous
#include <cuda_runtime.h>
#include <cuda_bf16.h>
#include <cstdint>

// Problem shape (fixed by reference): n=32, m=16, p=1024, d=512
//   task: [32, 16, 1024] f32
//   feat: [32, 1024, 512] f32
//   out : [32, 1024, 512] f32 = feat * mean_m(task)
#define N_DIM 32
#define M_DIM 16
#define P_DIM 1024
#define D_DIM 512

#define ROWS_PER_BLOCK 16                       // 16 rows * 128 f4 = 2048 f4/block
#define F4_PER_ROW (D_DIM / 4)                  // 128
#define F4_PER_BLOCK (ROWS_PER_BLOCK * F4_PER_ROW)   // 2048
#define NUM_BLOCKS ((N_DIM * P_DIM) / ROWS_PER_BLOCK) // 2048 blocks (~1.7 waves @ 8 CTA/SM)

// __launch_bounds__(256, 8): force <=32 regs so 8 CTAs (2048 threads) fit per
// SM -> 100% theoretical occupancy. Evidence (R2/R3/R5): DRAM% tracks
// occupancy on this kernel; warps are the cheap concurrency, not per-thread
// register batches.
__global__ void __launch_bounds__(256, 8) fused_kernel(const float* __restrict__ task,
                                                       const float4* __restrict__ feat,
                                                       float4* __restrict__ out) {
    __shared__ float s_scale[ROWS_PER_BLOCK];

    const int t = threadIdx.x;
    const int block_row0 = blockIdx.x * ROWS_PER_BLOCK;   // global row = n*1024 + p

    // ---- Phase 1: per-row mean over m (16 rows x 16 m = 256 loads, 1/thread) ----
    {
        const int row_local = t >> 4;     // 0..15
        const int m         = t & 15;     // 0..15
        const int grow = block_row0 + row_local;
        const int n = grow >> 10;
        const int p = grow & (P_DIM - 1);
        float v = task[((size_t)n * M_DIM + m) * P_DIM + p];
        #pragma unroll
        for (int off = 8; off; off >>= 1)
            v += __shfl_xor_sync(0xffffffffu, v, off, 16);
        if (m == 0) s_scale[row_local] = v * (1.0f / M_DIM);
    }
    __syncthreads();

    // ---- Phase 2: 2048 f4/block = 8 f4/thread, as 4 pairs (ILP 2, low regs) ----
    const size_t base = (size_t)block_row0 * F4_PER_ROW;

    #pragma unroll
    for (int k = 0; k < 4; ++k) {
        const int i0 = (2 * k) * 256 + t;
        const int i1 = (2 * k + 1) * 256 + t;
        float4 a = feat[base + (size_t)i0];
        float4 b = feat[base + (size_t)i1];
        const float sa = s_scale[i0 >> 7];
        const float sb = s_scale[i1 >> 7];
        a.x *= sa; a.y *= sa; a.z *= sa; a.w *= sa;
        b.x *= sb; b.y *= sb; b.z *= sb; b.w *= sb;
        // Evict-first streaming stores: keep feat L2-resident across replays
        // (proven ~2us win R2->R3).
        __stcs(&out[base + (size_t)i0], a);
        __stcs(&out[base + (size_t)i1], b);
    }
}

extern "C" void kernel_launch(void* const* d_in, const int* in_sizes, int n_in,
                              void* d_out, int out_size) {
    const float* task = (const float*)d_in[0];
    const float* feat = (const float*)d_in[1];
    float* out = (float*)d_out;

    fused_kernel<<<NUM_BLOCKS, 256>>>(task, (const float4*)feat, (float4*)out);
}